// round 12
// baseline (speedup 1.0000x reference)
#include <cuda_runtime.h>
#include <cuda_bf16.h>
#include <cstdint>
#include <cstddef>

// ===========================================================================
// LinkPrediction via mma.sync bf16 GEMMs with 3-term hi/lo fp32 emulation.
//   x = hi + lo (both bf16);  A@B ~= Ahi@Bhi + Ahi@Blo + Alo@Bhi  (fp32 accum)
// Edge head factorized: concat(emb[s],emb[d],yp)@pc1 = uAB[s,0:768]+uAB[d,768:1536]+t3[g]
// R12: PERSISTENT-TILE GEMM. grid = min(296, nTiles); each CTA walks tiles
//      bid, bid+grid, ... with ONE continuous 3-stage cp.async pipeline across
//      tile boundaries (chunk index c = tile*nk + k). Removes per-tile
//      prologue stalls (was: 1 tile per CTA = full DRAM fill each) and
//      overlaps epilogues with next tile's loads.  Core MMA config = R9 best
//      (BK=32, SW64, 2 CTAs/SM).
// ===========================================================================

#define NM    40000
#define DIMV  768
#define GMAXV 128
#define W768  (768*768)
#define W2304 (768*2304)

// ---------------- device scratch (allocation-free) -------------------------
__device__ __nv_bfloat16 g_Ah[NM*DIMV],   g_Al[NM*DIMV];
__device__ __nv_bfloat16 g_Bh[NM*DIMV],   g_Bl[NM*DIMV];
__device__ __nv_bfloat16 g_Ch[NM*3*DIMV], g_Cl[NM*3*DIMV];
__device__ float g_uAB[NM*2*DIMV];                   // fused [uA | uB]
__device__ float g_t3[GMAXV*DIMV];
__device__ __nv_bfloat16 g_yh[GMAXV*DIMV],  g_yl[GMAXV*DIMV];
__device__ __nv_bfloat16 g_yph[GMAXV*DIMV], g_ypl[GMAXV*DIMV];
__device__ float g_zero[2*DIMV];
__device__ __nv_bfloat16 g_ahT[2][W768], g_c0T[2][W768], g_c1T[2][W768], g_c2T[2][W768];
__device__ __nv_bfloat16 g_o1T[2][W2304];
__device__ __nv_bfloat16 g_o2T[2][W768], g_pyT[2][W768];
__device__ __nv_bfloat16 g_pABT[2][2*W768];          // fused [pc1_A^T ; pc1_B^T]
__device__ __nv_bfloat16 g_pCT[2][W768];

// ---------------- PTX helpers ----------------------------------------------
__device__ __forceinline__ uint32_t smem_u32(const void* p) {
    uint32_t a;
    asm("{ .reg .u64 t; cvta.to.shared.u64 t, %1; cvt.u32.u64 %0, t; }" : "=r"(a) : "l"(p));
    return a;
}
__device__ __forceinline__ void cpa16(uint32_t dst, const void* src) {
    asm volatile("cp.async.cg.shared.global [%0], [%1], 16;" :: "r"(dst), "l"(src));
}
#define CP_COMMIT() asm volatile("cp.async.commit_group;" ::: "memory")
#define CP_WAIT(n)  asm volatile("cp.async.wait_group %0;" :: "n"(n) : "memory")

__device__ __forceinline__ void ldsm4(uint32_t* r, uint32_t addr) {
    asm volatile("ldmatrix.sync.aligned.m8n8.x4.shared.b16 {%0,%1,%2,%3}, [%4];"
                 : "=r"(r[0]), "=r"(r[1]), "=r"(r[2]), "=r"(r[3]) : "r"(addr));
}
__device__ __forceinline__ void mma_bf16(float* c, const uint32_t* a, const uint32_t* b) {
    asm volatile(
        "mma.sync.aligned.m16n8k16.row.col.f32.bf16.bf16.f32 "
        "{%0,%1,%2,%3}, {%4,%5,%6,%7}, {%8,%9}, {%0,%1,%2,%3};"
        : "+f"(c[0]), "+f"(c[1]), "+f"(c[2]), "+f"(c[3])
        : "r"(a[0]), "r"(a[1]), "r"(a[2]), "r"(a[3]), "r"(b[0]), "r"(b[1]));
}
#define SWZ64(x) ((x) ^ (((x) >> 3) & 0x30))   // SW64 on byte offsets (64B rows)

// ---------------------------------------------------------------------------
// Persistent GEMM: D[M, Nn] = act(A[M,K] @ Wt^T + bias)
//   A hi/lo bf16 [M,K] (lda); Wt hi/lo bf16 [Nn,K] K-major.
//   FP32OUT=true : fp32 out to Cf.  false: hi/lo bf16 split to Chi/Clo.
//   act: 0 none, 1 relu, 3 leaky(0.4)
// 1-D grid of persistent CTAs; tiles (128x128) assigned round-robin; the
// 3-stage cp.async pipeline runs continuously across tile boundaries.
// BK=32, 256 thr (8 warps, 64x32 warp tiles), SW64 smem, 2 CTAs/SM.
// ---------------------------------------------------------------------------
#define STAGE_BYTES 32768

template<bool FP32OUT>
__global__ __launch_bounds__(256, 2)
void gemm_mma(const __nv_bfloat16* __restrict__ Ahi, const __nv_bfloat16* __restrict__ Alo,
              int lda,
              const __nv_bfloat16* __restrict__ Bhi, const __nv_bfloat16* __restrict__ Blo,
              const float* __restrict__ bias,
              float* __restrict__ Cf,
              __nv_bfloat16* __restrict__ Chi, __nv_bfloat16* __restrict__ Clo,
              int ldc, int M, int Nn, int K, int act)
{
    extern __shared__ char smem[];
    const uint32_t base = (smem_u32(smem) + 1023) & ~1023u;
    const int tid  = threadIdx.x;
    const int lane = tid & 31;
    const int w    = tid >> 5;
    const int warpM = w & 1;          // 2 warps along M
    const int warpN = w >> 1;         // 4 warps along N
    const int nk     = K / 32;
    const int tilesN = Nn >> 7;
    const int tilesM = (M + 127) >> 7;
    const int nTiles = tilesN * tilesM;
    const int grid   = gridDim.x;
    const int bid    = blockIdx.x;
    const int myTiles = (nTiles > bid) ? ((nTiles - bid + grid - 1) / grid) : 0;
    if (myTiles == 0) return;
    const int myC = myTiles * nk;

    // ---- chunk loader: chunk c = (local tile c/nk, k-slice c%nk) ----------
    auto chunk_load = [&](int c, int buf) {
        const int tl = c / nk;
        const int kk = c - tl * nk;
        const int gt = bid + tl * grid;
        const int bn = (gt % tilesN) << 7;
        const int bm = (gt / tilesN) << 7;
        const int k0 = kk * 32;
        const uint32_t tb = base + buf * STAGE_BYTES;
        #pragma unroll
        for (int t = 0; t < 2; t++) {
            const int u   = t * 256 + tid;        // 512 16B-units per tile
            const int row = u >> 2;
            const int col = (u & 3) * 8;          // element col within K32
            const uint32_t sw = SWZ64(row * 64 + col * 2);
            int ar = bm + row; if (ar >= M) ar = M - 1;   // clamp (never stored)
            const size_t aoff = (size_t)ar * lda + k0 + col;
            const size_t boff = (size_t)(bn + row) * K + k0 + col;
            cpa16(tb +         sw, Ahi + aoff);
            cpa16(tb +  8192 + sw, Alo + aoff);
            cpa16(tb + 16384 + sw, Bhi + boff);
            cpa16(tb + 24576 + sw, Blo + boff);
        }
        CP_COMMIT();
    };

    float acc[4][4][4];
    #pragma unroll
    for (int i = 0; i < 4; i++)
        #pragma unroll
        for (int j = 0; j < 4; j++)
            #pragma unroll
            for (int e = 0; e < 4; e++)
                acc[i][j][e] = 0.f;

    // per-lane ldmatrix address components (within-tile, before swizzle)
    const int aRow  = warpM * 64 + (lane & 15);                     // + mf*16
    const int aColE = ((lane >> 4) << 3);                           // + kf*16
    const int bRow  = warpN * 32 + ((lane >> 4) << 3) + (lane & 7); // + nfp*16
    const int bColE = ((lane >> 3) & 1) * 8;                        // + kf*16

    chunk_load(0, 0);
    if (myC > 1) chunk_load(1, 1);

    int kkRun = 0;      // k-slice within current tile
    int gt    = bid;    // current global tile

    for (int c = 0; c < myC; c++) {
        if (c + 1 < myC) { CP_WAIT(1); } else { CP_WAIT(0); }
        __syncthreads();   // all warps done with compute c-1 before
                           // buffer (c+2)%3 == (c-1)%3 refill below

        if (c + 2 < myC) chunk_load(c + 2, (c + 2) % 3);

        const uint32_t tb = base + (c % 3) * STAGE_BYTES;
        #pragma unroll
        for (int kf = 0; kf < 2; kf++) {
            uint32_t ah[4][4], al[4][4];
            #pragma unroll
            for (int mf = 0; mf < 4; mf++) {
                const uint32_t byte = SWZ64((aRow + mf * 16) * 64 + (aColE + kf * 16) * 2);
                ldsm4(ah[mf], tb + byte);
                ldsm4(al[mf], tb + 8192 + byte);
            }
            uint32_t bh[4][2], bl[4][2];
            #pragma unroll
            for (int nfp = 0; nfp < 2; nfp++) {
                const uint32_t byte = SWZ64((bRow + nfp * 16) * 64 + (bColE + kf * 16) * 2);
                uint32_t r[4];
                ldsm4(r, tb + 16384 + byte);
                bh[nfp*2][0] = r[0]; bh[nfp*2][1] = r[1];
                bh[nfp*2+1][0] = r[2]; bh[nfp*2+1][1] = r[3];
                ldsm4(r, tb + 24576 + byte);
                bl[nfp*2][0] = r[0]; bl[nfp*2][1] = r[1];
                bl[nfp*2+1][0] = r[2]; bl[nfp*2+1][1] = r[3];
            }
            #pragma unroll
            for (int mf = 0; mf < 4; mf++)
                #pragma unroll
                for (int nf = 0; nf < 4; nf++)
                    mma_bf16(acc[mf][nf], ah[mf], bh[nf]);
            #pragma unroll
            for (int mf = 0; mf < 4; mf++)
                #pragma unroll
                for (int nf = 0; nf < 4; nf++)
                    mma_bf16(acc[mf][nf], ah[mf], bl[nf]);
            #pragma unroll
            for (int mf = 0; mf < 4; mf++)
                #pragma unroll
                for (int nf = 0; nf < 4; nf++)
                    mma_bf16(acc[mf][nf], al[mf], bh[nf]);
        }

        // ---- tile boundary: epilogue + accumulator reset ------------------
        if (++kkRun == nk) {
            const int bn = (gt % tilesN) << 7;
            const int bm = (gt / tilesN) << 7;
            #pragma unroll
            for (int mf = 0; mf < 4; mf++) {
                #pragma unroll
                for (int half = 0; half < 2; half++) {
                    const int row = bm + warpM * 64 + mf * 16 + (lane >> 2) + half * 8;
                    if (row < M) {
                        #pragma unroll
                        for (int nf = 0; nf < 4; nf++) {
                            const int col = bn + warpN * 32 + nf * 8 + (lane & 3) * 2;
                            const float2 bi = *(const float2*)(bias + col);
                            float v0 = acc[mf][nf][half * 2 + 0] + bi.x;
                            float v1 = acc[mf][nf][half * 2 + 1] + bi.y;
                            if (act == 1) { v0 = fmaxf(v0, 0.f); v1 = fmaxf(v1, 0.f); }
                            else if (act == 3) { v0 = (v0 > 0.f) ? v0 : 0.4f * v0;
                                                 v1 = (v1 > 0.f) ? v1 : 0.4f * v1; }
                            if (FP32OUT) {
                                float2 o; o.x = v0; o.y = v1;
                                *(float2*)(Cf + (size_t)row * ldc + col) = o;
                            } else {
                                const __nv_bfloat16 h0 = __float2bfloat16(v0);
                                const __nv_bfloat16 h1 = __float2bfloat16(v1);
                                __nv_bfloat162 hh; hh.x = h0; hh.y = h1;
                                __nv_bfloat162 ll;
                                ll.x = __float2bfloat16(v0 - __bfloat162float(h0));
                                ll.y = __float2bfloat16(v1 - __bfloat162float(h1));
                                *(__nv_bfloat162*)(Chi + (size_t)row * ldc + col) = hh;
                                *(__nv_bfloat162*)(Clo + (size_t)row * ldc + col) = ll;
                            }
                        }
                    }
                }
            }
            #pragma unroll
            for (int i = 0; i < 4; i++)
                #pragma unroll
                for (int j = 0; j < 4; j++)
                    #pragma unroll
                    for (int e = 0; e < 4; e++)
                        acc[i][j][e] = 0.f;
            kkRun = 0;
            gt += grid;
        }
    }
}

// ---------------------------------------------------------------------------
// Batched weight transpose + hi/lo split. Each job transposes a 768x768 block
// W[k, n] into hi/lo[n * Kout + k_off + k]. o1 = 3 jobs with Kout=2304.
// ---------------------------------------------------------------------------
struct WJob  { const float* W; __nv_bfloat16* hi; __nv_bfloat16* lo; int Kout; int k_off; };
struct WJobs { WJob j[12]; };

__global__ void wsplit_batch(WJobs jobs)
{
    __shared__ float t[32][33];
    const WJob jb = jobs.j[blockIdx.z];
    const int Nn = 768;
    const int k0 = blockIdx.x * 32, n0 = blockIdx.y * 32;
    const int tx = threadIdx.x, ty = threadIdx.y;
    #pragma unroll
    for (int i = 0; i < 32; i += 8)
        t[ty + i][tx] = jb.W[(size_t)(k0 + ty + i) * Nn + n0 + tx];
    __syncthreads();
    #pragma unroll
    for (int i = 0; i < 32; i += 8) {
        const float v = t[tx][ty + i];
        const __nv_bfloat16 h = __float2bfloat16(v);
        const size_t o = (size_t)(n0 + ty + i) * jb.Kout + jb.k_off + k0 + tx;
        jb.hi[o] = h;
        jb.lo[o] = __float2bfloat16(v - __bfloat162float(h));
    }
}

__global__ void fsplit(const float* __restrict__ s, __nv_bfloat16* __restrict__ hi,
                       __nv_bfloat16* __restrict__ lo, int n)
{
    const int i = blockIdx.x * blockDim.x + threadIdx.x;
    if (i < n) {
        const float v = s[i];
        const __nv_bfloat16 h = __float2bfloat16(v);
        hi[i] = h;
        lo[i] = __float2bfloat16(v - __bfloat162float(h));
    }
}

// ---------------------------------------------------------------------------
// Edge head: one warp per edge; uAB holds [uA | uB] rows of 1536.
// ---------------------------------------------------------------------------
__global__ __launch_bounds__(256)
void edge_kernel(const float* __restrict__ uAB,
                 const float* __restrict__ t3,
                 const int* __restrict__ edge_index, const int* __restrict__ batch,
                 const float* __restrict__ w2, const float* __restrict__ b2,
                 const float* __restrict__ label, float* __restrict__ out, int E)
{
    const int e = blockIdx.x * 8 + (threadIdx.x >> 5);
    if (e >= E) return;
    const int lane = threadIdx.x & 31;
    const int s = edge_index[e];
    const int d = edge_index[E + e];
    const int g = batch[s];

    const float4* a = (const float4*)(uAB + (size_t)s * (2 * DIMV));
    const float4* b = (const float4*)(uAB + (size_t)d * (2 * DIMV) + DIMV);
    const float4* t = (const float4*)(t3 + (size_t)g * DIMV);
    const float4* wv = (const float4*)w2;

    float p0 = 0.f, p1 = 0.f;
    #pragma unroll
    for (int it = 0; it < 6; it++) {
        const int q = it * 32 + lane;
        float4 av = a[q], bv = b[q], tv = t[q];
        float4 w0 = wv[2 * q], w1 = wv[2 * q + 1];
        float v0 = fmaxf(av.x + bv.x + tv.x, 0.f);
        float v1 = fmaxf(av.y + bv.y + tv.y, 0.f);
        float v2 = fmaxf(av.z + bv.z + tv.z, 0.f);
        float v3 = fmaxf(av.w + bv.w + tv.w, 0.f);
        p0 = fmaf(v0, w0.x, p0); p0 = fmaf(v1, w0.z, p0);
        p0 = fmaf(v2, w1.x, p0); p0 = fmaf(v3, w1.z, p0);
        p1 = fmaf(v0, w0.y, p1); p1 = fmaf(v1, w0.w, p1);
        p1 = fmaf(v2, w1.y, p1); p1 = fmaf(v3, w1.w, p1);
    }
    #pragma unroll
    for (int o = 16; o > 0; o >>= 1) {
        p0 += __shfl_xor_sync(0xFFFFFFFFu, p0, o);
        p1 += __shfl_xor_sync(0xFFFFFFFFu, p1, o);
    }
    if (lane == 0) {
        out[2 * e]     = 1.f / (1.f + expf(-(p0 + b2[0])));
        out[2 * e + 1] = 1.f / (1.f + expf(-(p1 + b2[1])));
        out[2 * E + e] = label[e];
    }
}

// ---------------------------------------------------------------------------
// Host launcher.  Stream order: 0-2 prep, 3-11 gemm_mma, 12 edge.
// ---------------------------------------------------------------------------
static const int SMEM_BYTES = 1024 + 3 * STAGE_BYTES;   // 99328 per CTA
static const int PERSIST_CTAS = 296;                    // 2 per SM x 148 SMs

static inline int pgrid(int tiles) { return tiles < PERSIST_CTAS ? tiles : PERSIST_CTAS; }

extern "C" void kernel_launch(void* const* d_in, const int* in_sizes, int n_in,
                              void* d_out, int out_size)
{
    const float* x     = (const float*)d_in[0];
    const int*   ei    = (const int*)  d_in[1];
    const int*   batch = (const int*)  d_in[2];
    const float* y     = (const float*)d_in[5];
    const float* label = (const float*)d_in[6];
    const float* ahW = (const float*)d_in[7],  *ahb = (const float*)d_in[8];
    const float* c0W = (const float*)d_in[9],  *c0b = (const float*)d_in[10];
    const float* c1W = (const float*)d_in[11], *c1b = (const float*)d_in[12];
    const float* c2W = (const float*)d_in[13], *c2b = (const float*)d_in[14];
    const float* o1W = (const float*)d_in[15], *o1b = (const float*)d_in[16];
    const float* o2W = (const float*)d_in[17], *o2b = (const float*)d_in[18];
    const float* pyW = (const float*)d_in[19], *pyb = (const float*)d_in[20];
    const float* pc1W = (const float*)d_in[21], *pc1b = (const float*)d_in[22];
    const float* pc2W = (const float*)d_in[23], *pc2b = (const float*)d_in[24];
    float* out = (float*)d_out;

    const int N = in_sizes[2];
    const int E = in_sizes[6];
    const int G = in_sizes[5] / DIMV;
    (void)n_in; (void)out_size;

    __nv_bfloat16 *Ah, *Al, *Bh, *Bl, *Ch, *Cl, *yh, *yl, *yph, *ypl;
    float *uAB, *t3, *zero;
    __nv_bfloat16 (*ahT)[W768], (*c0T)[W768], (*c1T)[W768], (*c2T)[W768],
                  (*o2T)[W768], (*pyT)[W768], (*pCT)[W768];
    __nv_bfloat16 (*o1T)[W2304];
    __nv_bfloat16 (*pABT)[2*W768];
    cudaGetSymbolAddress((void**)&Ah, g_Ah);   cudaGetSymbolAddress((void**)&Al, g_Al);
    cudaGetSymbolAddress((void**)&Bh, g_Bh);   cudaGetSymbolAddress((void**)&Bl, g_Bl);
    cudaGetSymbolAddress((void**)&Ch, g_Ch);   cudaGetSymbolAddress((void**)&Cl, g_Cl);
    cudaGetSymbolAddress((void**)&yh, g_yh);   cudaGetSymbolAddress((void**)&yl, g_yl);
    cudaGetSymbolAddress((void**)&yph, g_yph); cudaGetSymbolAddress((void**)&ypl, g_ypl);
    cudaGetSymbolAddress((void**)&uAB, g_uAB);
    cudaGetSymbolAddress((void**)&t3, g_t3);   cudaGetSymbolAddress((void**)&zero, g_zero);
    cudaGetSymbolAddress((void**)&ahT, g_ahT); cudaGetSymbolAddress((void**)&c0T, g_c0T);
    cudaGetSymbolAddress((void**)&c1T, g_c1T); cudaGetSymbolAddress((void**)&c2T, g_c2T);
    cudaGetSymbolAddress((void**)&o1T, g_o1T); cudaGetSymbolAddress((void**)&o2T, g_o2T);
    cudaGetSymbolAddress((void**)&pyT, g_pyT); cudaGetSymbolAddress((void**)&pABT, g_pABT);
    cudaGetSymbolAddress((void**)&pCT, g_pCT);

    cudaFuncSetAttribute(gemm_mma<true>,  cudaFuncAttributeMaxDynamicSharedMemorySize, SMEM_BYTES);
    cudaFuncSetAttribute(gemm_mma<false>, cudaFuncAttributeMaxDynamicSharedMemorySize, SMEM_BYTES);

    const int mt = (N + 127) / 128;
    const int gN  = pgrid(6 * mt);    // encoder GEMMs: Nn=768
    const int gAB = pgrid(12 * mt);   // fused uAB: Nn=1536
    const int gG  = pgrid(6 * 1);     // graph GEMMs (G=128 rows)
    dim3 blk(256), wb(32, 8);

    // ---- launches 0-2: all prep ------------------------------------------
    fsplit<<<(N * DIMV + 255) / 256, 256>>>(x, Bh, Bl, N * DIMV);          // 0
    fsplit<<<(G * DIMV + 255) / 256, 256>>>(y, yh, yl, G * DIMV);          // 1

    WJobs jb;
    jb.j[0]  = { ahW,               ahT[0],         ahT[1],          768,  0    };
    jb.j[1]  = { c0W,               c0T[0],         c0T[1],          768,  0    };
    jb.j[2]  = { c1W,               c1T[0],         c1T[1],          768,  0    };
    jb.j[3]  = { c2W,               c2T[0],         c2T[1],          768,  0    };
    jb.j[4]  = { o2W,               o2T[0],         o2T[1],          768,  0    };
    jb.j[5]  = { pyW,               pyT[0],         pyT[1],          768,  0    };
    jb.j[6]  = { pc1W,              pABT[0],        pABT[1],         768,  0    };
    jb.j[7]  = { pc1W + 768 * 768,  pABT[0] + W768, pABT[1] + W768,  768,  0    };
    jb.j[8]  = { pc1W + 1536 * 768, pCT[0],         pCT[1],          768,  0    };
    jb.j[9]  = { o1W,               o1T[0],         o1T[1],          2304, 0    };
    jb.j[10] = { o1W + 768 * 768,   o1T[0],         o1T[1],          2304, 768  };
    jb.j[11] = { o1W + 1536 * 768,  o1T[0],         o1T[1],          2304, 1536 };
    wsplit_batch<<<dim3(24, 24, 12), wb>>>(jb);                            // 2

    // ---- launches 3-11: ALL gemm_mma (persistent) -------------------------
    gemm_mma<false><<<gN, blk, SMEM_BYTES>>>(Bh, Bl, DIMV, ahT[0], ahT[1], ahb,
                                             nullptr, Ah, Al, DIMV, N, DIMV, DIMV, 1);   // 3
    gemm_mma<false><<<gN, blk, SMEM_BYTES>>>(Ah, Al, DIMV, c0T[0], c0T[1], c0b,
                                             nullptr, Ch, Cl, 3 * DIMV, N, DIMV, DIMV, 1); // 4
    gemm_mma<false><<<gN, blk, SMEM_BYTES>>>(Ch, Cl, 3 * DIMV, c1T[0], c1T[1], c1b,
                                             nullptr, Ch + DIMV, Cl + DIMV, 3 * DIMV, N, DIMV, DIMV, 1); // 5
    gemm_mma<false><<<gN, blk, SMEM_BYTES>>>(Ch + DIMV, Cl + DIMV, 3 * DIMV, c2T[0], c2T[1], c2b,
                                             nullptr, Ch + 2 * DIMV, Cl + 2 * DIMV, 3 * DIMV, N, DIMV, DIMV, 1); // 6
    gemm_mma<false><<<gN, blk, SMEM_BYTES>>>(Ch, Cl, 3 * DIMV, o1T[0], o1T[1], o1b,
                                             nullptr, Ah, Al, DIMV, N, DIMV, 3 * DIMV, 1); // 7
    gemm_mma<false><<<gN, blk, SMEM_BYTES>>>(Ah, Al, DIMV, o2T[0], o2T[1], o2b,
                                             nullptr, Bh, Bl, DIMV, N, DIMV, DIMV, 0);   // 8
    gemm_mma<true><<<gAB, blk, SMEM_BYTES>>>(Bh, Bl, DIMV, pABT[0], pABT[1], zero,
                                             uAB, nullptr, nullptr, 2 * DIMV, N, 2 * DIMV, DIMV, 0); // 9
    gemm_mma<false><<<gG, blk, SMEM_BYTES>>>(yh, yl, DIMV, pyT[0], pyT[1], pyb,
                                             nullptr, yph, ypl, DIMV, G, DIMV, DIMV, 3); // 10
    gemm_mma<true><<<gG, blk, SMEM_BYTES>>>(yph, ypl, DIMV, pCT[0], pCT[1], pc1b,
                                            t3, nullptr, nullptr, DIMV, G, DIMV, DIMV, 0); // 11

    // ---- launch 12: edge head --------------------------------------------
    edge_kernel<<<(E + 7) / 8, 256>>>(uAB, t3, ei, batch, pc2W, pc2b, label, out, E);
}

// round 13
// speedup vs baseline: 1.1182x; 1.1182x over previous
#include <cuda_runtime.h>
#include <cuda_bf16.h>
#include <cstdint>
#include <cstddef>

// ===========================================================================
// LinkPrediction via mma.sync bf16 GEMMs with 3-term hi/lo fp32 emulation.
//   x = hi + lo (both bf16);  A@B ~= Ahi@Bhi + Ahi@Blo + Alo@Bhi  (fp32 accum)
// Edge head factorized: concat(emb[s],emb[d],yp)@pc1 = uAB[s,0:768]+uAB[d,768:1536]+t3[g]
// R13: revert to R11 structure (best: 3849us, tensor=68%); add
//   * fully hoisted loader addressing (only +32*j per chunk),
//   * next-chunk cp.async issued BETWEEN kf groups (post-barrier LDSMs first),
//   * NK (K/32) as template param, unroll 3 so %3 buffer indices are constant.
// ===========================================================================

#define NM    40000
#define DIMV  768
#define GMAXV 128
#define W768  (768*768)
#define W2304 (768*2304)

// ---------------- device scratch (allocation-free) -------------------------
__device__ __nv_bfloat16 g_Ah[NM*DIMV],   g_Al[NM*DIMV];
__device__ __nv_bfloat16 g_Bh[NM*DIMV],   g_Bl[NM*DIMV];
__device__ __nv_bfloat16 g_Ch[NM*3*DIMV], g_Cl[NM*3*DIMV];
__device__ float g_uAB[NM*2*DIMV];                   // fused [uA | uB]
__device__ float g_t3[GMAXV*DIMV];
__device__ __nv_bfloat16 g_yh[GMAXV*DIMV],  g_yl[GMAXV*DIMV];
__device__ __nv_bfloat16 g_yph[GMAXV*DIMV], g_ypl[GMAXV*DIMV];
__device__ float g_zero[2*DIMV];
__device__ __nv_bfloat16 g_ahT[2][W768], g_c0T[2][W768], g_c1T[2][W768], g_c2T[2][W768];
__device__ __nv_bfloat16 g_o1T[2][W2304];
__device__ __nv_bfloat16 g_o2T[2][W768], g_pyT[2][W768];
__device__ __nv_bfloat16 g_pABT[2][2*W768];          // fused [pc1_A^T ; pc1_B^T]
__device__ __nv_bfloat16 g_pCT[2][W768];

// ---------------- PTX helpers ----------------------------------------------
__device__ __forceinline__ uint32_t smem_u32(const void* p) {
    uint32_t a;
    asm("{ .reg .u64 t; cvta.to.shared.u64 t, %1; cvt.u32.u64 %0, t; }" : "=r"(a) : "l"(p));
    return a;
}
__device__ __forceinline__ void cpa16(uint32_t dst, const void* src) {
    asm volatile("cp.async.cg.shared.global [%0], [%1], 16;" :: "r"(dst), "l"(src));
}
#define CP_COMMIT() asm volatile("cp.async.commit_group;" ::: "memory")
#define CP_WAIT(n)  asm volatile("cp.async.wait_group %0;" :: "n"(n) : "memory")

__device__ __forceinline__ void ldsm4(uint32_t* r, uint32_t addr) {
    asm volatile("ldmatrix.sync.aligned.m8n8.x4.shared.b16 {%0,%1,%2,%3}, [%4];"
                 : "=r"(r[0]), "=r"(r[1]), "=r"(r[2]), "=r"(r[3]) : "r"(addr));
}
__device__ __forceinline__ void mma_bf16(float* c, const uint32_t* a, const uint32_t* b) {
    asm volatile(
        "mma.sync.aligned.m16n8k16.row.col.f32.bf16.bf16.f32 "
        "{%0,%1,%2,%3}, {%4,%5,%6,%7}, {%8,%9}, {%0,%1,%2,%3};"
        : "+f"(c[0]), "+f"(c[1]), "+f"(c[2]), "+f"(c[3])
        : "r"(a[0]), "r"(a[1]), "r"(a[2]), "r"(a[3]), "r"(b[0]), "r"(b[1]));
}
#define SWZ64(x) ((x) ^ (((x) >> 3) & 0x30))   // SW64 on byte offsets (64B rows)

// ---------------------------------------------------------------------------
// GEMM: D[M, Nn] = act(A[M,K] @ Wt^T + bias), grid = (Nn/128, ceil(M/128))
//   A hi/lo bf16 [M,K] (lda); Wt hi/lo bf16 [Nn,K] K-major.  K = 32*NK.
//   FP32OUT=true : fp32 out to Cf.  false: hi/lo bf16 split to Chi/Clo.
//   act: 0 none, 1 relu, 3 leaky(0.4)
// BM=BN=128, BK=32, 256 thr (8 warps, 64x32 warp tiles), SW64 smem,
// 3-stage cp.async, ONE __syncthreads per iteration, 2 CTAs/SM.
// ---------------------------------------------------------------------------
#define STAGE_BYTES 32768

template<bool FP32OUT, int NK>
__global__ __launch_bounds__(256, 2)
void gemm_mma(const __nv_bfloat16* __restrict__ Ahi, const __nv_bfloat16* __restrict__ Alo,
              int lda,
              const __nv_bfloat16* __restrict__ Bhi, const __nv_bfloat16* __restrict__ Blo,
              const float* __restrict__ bias,
              float* __restrict__ Cf,
              __nv_bfloat16* __restrict__ Chi, __nv_bfloat16* __restrict__ Clo,
              int ldc, int M, int act)
{
    constexpr int K = 32 * NK;
    extern __shared__ char smem[];
    const uint32_t base = (smem_u32(smem) + 1023) & ~1023u;
    const int tid  = threadIdx.x;
    const int lane = tid & 31;
    const int w    = tid >> 5;
    const int warpM = w & 1;          // 2 warps along M
    const int warpN = w >> 1;         // 4 warps along N
    const int bm = blockIdx.y * 128;
    const int bn = blockIdx.x * 128;

    // ---- hoisted loader addressing (chunk-invariant) ----------------------
    // 512 16B-units per 8KB tile; thread handles units tid and tid+256.
    const int lRow0 = tid >> 2;               // rows 0..63
    const int lRow1 = lRow0 + 64;             // rows 64..127
    const int lCol  = (tid & 3) * 8;          // element col within K32
    const uint32_t sw0 = SWZ64(lRow0 * 64 + lCol * 2);
    const uint32_t sw1 = SWZ64(lRow1 * 64 + lCol * 2);
    int ar0 = bm + lRow0; if (ar0 >= M) ar0 = M - 1;     // clamp (never stored)
    int ar1 = bm + lRow1; if (ar1 >= M) ar1 = M - 1;
    const size_t aOff0 = (size_t)ar0 * lda + lCol;
    const size_t aOff1 = (size_t)ar1 * lda + lCol;
    const size_t bOff0 = (size_t)(bn + lRow0) * K + lCol;
    const size_t bOff1 = (size_t)(bn + lRow1) * K + lCol;

    auto load_stage = [&](int j, int buf) {
        const int k0 = j * 32;
        const uint32_t tb = base + buf * STAGE_BYTES;
        cpa16(tb +         sw0, Ahi + aOff0 + k0);
        cpa16(tb +  8192 + sw0, Alo + aOff0 + k0);
        cpa16(tb + 16384 + sw0, Bhi + bOff0 + k0);
        cpa16(tb + 24576 + sw0, Blo + bOff0 + k0);
        cpa16(tb +         sw1, Ahi + aOff1 + k0);
        cpa16(tb +  8192 + sw1, Alo + aOff1 + k0);
        cpa16(tb + 16384 + sw1, Bhi + bOff1 + k0);
        cpa16(tb + 24576 + sw1, Blo + bOff1 + k0);
        CP_COMMIT();
    };

    float acc[4][4][4];
    #pragma unroll
    for (int i = 0; i < 4; i++)
        #pragma unroll
        for (int j = 0; j < 4; j++)
            #pragma unroll
            for (int e = 0; e < 4; e++)
                acc[i][j][e] = 0.f;

    // per-lane ldmatrix address components (within-tile, before swizzle)
    const int aRow  = warpM * 64 + (lane & 15);                     // + mf*16
    const int aColE = ((lane >> 4) << 3);                           // + kf*16
    const int bRow  = warpN * 32 + ((lane >> 4) << 3) + (lane & 7); // + nfp*16
    const int bColE = ((lane >> 3) & 1) * 8;                        // + kf*16

    // one kf group: 12 LDSM + 48 HMMA on buffer tb
    auto compute_kf = [&](uint32_t tb, int kf) {
        uint32_t ah[4][4], al[4][4];
        #pragma unroll
        for (int mf = 0; mf < 4; mf++) {
            const uint32_t byte = SWZ64((aRow + mf * 16) * 64 + (aColE + kf * 16) * 2);
            ldsm4(ah[mf], tb + byte);
            ldsm4(al[mf], tb + 8192 + byte);
        }
        uint32_t bh[4][2], bl[4][2];
        #pragma unroll
        for (int nfp = 0; nfp < 2; nfp++) {
            const uint32_t byte = SWZ64((bRow + nfp * 16) * 64 + (bColE + kf * 16) * 2);
            uint32_t r[4];
            ldsm4(r, tb + 16384 + byte);
            bh[nfp*2][0] = r[0]; bh[nfp*2][1] = r[1];
            bh[nfp*2+1][0] = r[2]; bh[nfp*2+1][1] = r[3];
            ldsm4(r, tb + 24576 + byte);
            bl[nfp*2][0] = r[0]; bl[nfp*2][1] = r[1];
            bl[nfp*2+1][0] = r[2]; bl[nfp*2+1][1] = r[3];
        }
        #pragma unroll
        for (int mf = 0; mf < 4; mf++)
            #pragma unroll
            for (int nf = 0; nf < 4; nf++)
                mma_bf16(acc[mf][nf], ah[mf], bh[nf]);
        #pragma unroll
        for (int mf = 0; mf < 4; mf++)
            #pragma unroll
            for (int nf = 0; nf < 4; nf++)
                mma_bf16(acc[mf][nf], ah[mf], bl[nf]);
        #pragma unroll
        for (int mf = 0; mf < 4; mf++)
            #pragma unroll
            for (int nf = 0; nf < 4; nf++)
                mma_bf16(acc[mf][nf], al[mf], bh[nf]);
    };

    load_stage(0, 0);
    load_stage(1, 1);

    #pragma unroll 3
    for (int i = 0; i < NK; i++) {
        if (i + 1 < NK) { CP_WAIT(1); } else { CP_WAIT(0); }
        __syncthreads();   // all warps done with compute i-1 before
                           // buffer (i+2)%3 == (i-1)%3 refill below

        const uint32_t tb = base + (i % 3) * STAGE_BYTES;
        compute_kf(tb, 0);
        // issue next chunk's loads AFTER this chunk's first LDSM burst:
        // the loads have 2 chunks of slack, the LDSMs have none.
        if (i + 2 < NK) load_stage(i + 2, (i + 2) % 3);
        compute_kf(tb, 1);
    }

    // ---------------- epilogue (registers -> global, no smem) --------------
    #pragma unroll
    for (int mf = 0; mf < 4; mf++) {
        #pragma unroll
        for (int half = 0; half < 2; half++) {
            const int row = bm + warpM * 64 + mf * 16 + (lane >> 2) + half * 8;
            if (row < M) {
                #pragma unroll
                for (int nf = 0; nf < 4; nf++) {
                    const int col = bn + warpN * 32 + nf * 8 + (lane & 3) * 2;
                    const float2 bi = *(const float2*)(bias + col);
                    float v0 = acc[mf][nf][half * 2 + 0] + bi.x;
                    float v1 = acc[mf][nf][half * 2 + 1] + bi.y;
                    if (act == 1) { v0 = fmaxf(v0, 0.f); v1 = fmaxf(v1, 0.f); }
                    else if (act == 3) { v0 = (v0 > 0.f) ? v0 : 0.4f * v0;
                                         v1 = (v1 > 0.f) ? v1 : 0.4f * v1; }
                    if (FP32OUT) {
                        float2 o; o.x = v0; o.y = v1;
                        *(float2*)(Cf + (size_t)row * ldc + col) = o;
                    } else {
                        const __nv_bfloat16 h0 = __float2bfloat16(v0);
                        const __nv_bfloat16 h1 = __float2bfloat16(v1);
                        __nv_bfloat162 hh; hh.x = h0; hh.y = h1;
                        __nv_bfloat162 ll;
                        ll.x = __float2bfloat16(v0 - __bfloat162float(h0));
                        ll.y = __float2bfloat16(v1 - __bfloat162float(h1));
                        *(__nv_bfloat162*)(Chi + (size_t)row * ldc + col) = hh;
                        *(__nv_bfloat162*)(Clo + (size_t)row * ldc + col) = ll;
                    }
                }
            }
        }
    }
}

// ---------------------------------------------------------------------------
// Batched weight transpose + hi/lo split. Each job transposes a 768x768 block
// W[k, n] into hi/lo[n * Kout + k_off + k]. o1 = 3 jobs with Kout=2304.
// ---------------------------------------------------------------------------
struct WJob  { const float* W; __nv_bfloat16* hi; __nv_bfloat16* lo; int Kout; int k_off; };
struct WJobs { WJob j[12]; };

__global__ void wsplit_batch(WJobs jobs)
{
    __shared__ float t[32][33];
    const WJob jb = jobs.j[blockIdx.z];
    const int Nn = 768;
    const int k0 = blockIdx.x * 32, n0 = blockIdx.y * 32;
    const int tx = threadIdx.x, ty = threadIdx.y;
    #pragma unroll
    for (int i = 0; i < 32; i += 8)
        t[ty + i][tx] = jb.W[(size_t)(k0 + ty + i) * Nn + n0 + tx];
    __syncthreads();
    #pragma unroll
    for (int i = 0; i < 32; i += 8) {
        const float v = t[tx][ty + i];
        const __nv_bfloat16 h = __float2bfloat16(v);
        const size_t o = (size_t)(n0 + ty + i) * jb.Kout + jb.k_off + k0 + tx;
        jb.hi[o] = h;
        jb.lo[o] = __float2bfloat16(v - __bfloat162float(h));
    }
}

__global__ void fsplit(const float* __restrict__ s, __nv_bfloat16* __restrict__ hi,
                       __nv_bfloat16* __restrict__ lo, int n)
{
    const int i = blockIdx.x * blockDim.x + threadIdx.x;
    if (i < n) {
        const float v = s[i];
        const __nv_bfloat16 h = __float2bfloat16(v);
        hi[i] = h;
        lo[i] = __float2bfloat16(v - __bfloat162float(h));
    }
}

// ---------------------------------------------------------------------------
// Edge head: one warp per edge; uAB holds [uA | uB] rows of 1536.
// ---------------------------------------------------------------------------
__global__ __launch_bounds__(256)
void edge_kernel(const float* __restrict__ uAB,
                 const float* __restrict__ t3,
                 const int* __restrict__ edge_index, const int* __restrict__ batch,
                 const float* __restrict__ w2, const float* __restrict__ b2,
                 const float* __restrict__ label, float* __restrict__ out, int E)
{
    const int e = blockIdx.x * 8 + (threadIdx.x >> 5);
    if (e >= E) return;
    const int lane = threadIdx.x & 31;
    const int s = edge_index[e];
    const int d = edge_index[E + e];
    const int g = batch[s];

    const float4* a = (const float4*)(uAB + (size_t)s * (2 * DIMV));
    const float4* b = (const float4*)(uAB + (size_t)d * (2 * DIMV) + DIMV);
    const float4* t = (const float4*)(t3 + (size_t)g * DIMV);
    const float4* wv = (const float4*)w2;

    float p0 = 0.f, p1 = 0.f;
    #pragma unroll
    for (int it = 0; it < 6; it++) {
        const int q = it * 32 + lane;
        float4 av = a[q], bv = b[q], tv = t[q];
        float4 w0 = wv[2 * q], w1 = wv[2 * q + 1];
        float v0 = fmaxf(av.x + bv.x + tv.x, 0.f);
        float v1 = fmaxf(av.y + bv.y + tv.y, 0.f);
        float v2 = fmaxf(av.z + bv.z + tv.z, 0.f);
        float v3 = fmaxf(av.w + bv.w + tv.w, 0.f);
        p0 = fmaf(v0, w0.x, p0); p0 = fmaf(v1, w0.z, p0);
        p0 = fmaf(v2, w1.x, p0); p0 = fmaf(v3, w1.z, p0);
        p1 = fmaf(v0, w0.y, p1); p1 = fmaf(v1, w0.w, p1);
        p1 = fmaf(v2, w1.y, p1); p1 = fmaf(v3, w1.w, p1);
    }
    #pragma unroll
    for (int o = 16; o > 0; o >>= 1) {
        p0 += __shfl_xor_sync(0xFFFFFFFFu, p0, o);
        p1 += __shfl_xor_sync(0xFFFFFFFFu, p1, o);
    }
    if (lane == 0) {
        out[2 * e]     = 1.f / (1.f + expf(-(p0 + b2[0])));
        out[2 * e + 1] = 1.f / (1.f + expf(-(p1 + b2[1])));
        out[2 * E + e] = label[e];
    }
}

// ---------------------------------------------------------------------------
// Host launcher.  Stream order: 0-2 prep, 3-11 gemm_mma, 12 edge.
// ---------------------------------------------------------------------------
static const int SMEM_BYTES = 1024 + 3 * STAGE_BYTES;   // 99328 per CTA

extern "C" void kernel_launch(void* const* d_in, const int* in_sizes, int n_in,
                              void* d_out, int out_size)
{
    const float* x     = (const float*)d_in[0];
    const int*   ei    = (const int*)  d_in[1];
    const int*   batch = (const int*)  d_in[2];
    const float* y     = (const float*)d_in[5];
    const float* label = (const float*)d_in[6];
    const float* ahW = (const float*)d_in[7],  *ahb = (const float*)d_in[8];
    const float* c0W = (const float*)d_in[9],  *c0b = (const float*)d_in[10];
    const float* c1W = (const float*)d_in[11], *c1b = (const float*)d_in[12];
    const float* c2W = (const float*)d_in[13], *c2b = (const float*)d_in[14];
    const float* o1W = (const float*)d_in[15], *o1b = (const float*)d_in[16];
    const float* o2W = (const float*)d_in[17], *o2b = (const float*)d_in[18];
    const float* pyW = (const float*)d_in[19], *pyb = (const float*)d_in[20];
    const float* pc1W = (const float*)d_in[21], *pc1b = (const float*)d_in[22];
    const float* pc2W = (const float*)d_in[23], *pc2b = (const float*)d_in[24];
    float* out = (float*)d_out;

    const int N = in_sizes[2];
    const int E = in_sizes[6];
    const int G = in_sizes[5] / DIMV;
    (void)n_in; (void)out_size;

    __nv_bfloat16 *Ah, *Al, *Bh, *Bl, *Ch, *Cl, *yh, *yl, *yph, *ypl;
    float *uAB, *t3, *zero;
    __nv_bfloat16 (*ahT)[W768], (*c0T)[W768], (*c1T)[W768], (*c2T)[W768],
                  (*o2T)[W768], (*pyT)[W768], (*pCT)[W768];
    __nv_bfloat16 (*o1T)[W2304];
    __nv_bfloat16 (*pABT)[2*W768];
    cudaGetSymbolAddress((void**)&Ah, g_Ah);   cudaGetSymbolAddress((void**)&Al, g_Al);
    cudaGetSymbolAddress((void**)&Bh, g_Bh);   cudaGetSymbolAddress((void**)&Bl, g_Bl);
    cudaGetSymbolAddress((void**)&Ch, g_Ch);   cudaGetSymbolAddress((void**)&Cl, g_Cl);
    cudaGetSymbolAddress((void**)&yh, g_yh);   cudaGetSymbolAddress((void**)&yl, g_yl);
    cudaGetSymbolAddress((void**)&yph, g_yph); cudaGetSymbolAddress((void**)&ypl, g_ypl);
    cudaGetSymbolAddress((void**)&uAB, g_uAB);
    cudaGetSymbolAddress((void**)&t3, g_t3);   cudaGetSymbolAddress((void**)&zero, g_zero);
    cudaGetSymbolAddress((void**)&ahT, g_ahT); cudaGetSymbolAddress((void**)&c0T, g_c0T);
    cudaGetSymbolAddress((void**)&c1T, g_c1T); cudaGetSymbolAddress((void**)&c2T, g_c2T);
    cudaGetSymbolAddress((void**)&o1T, g_o1T); cudaGetSymbolAddress((void**)&o2T, g_o2T);
    cudaGetSymbolAddress((void**)&pyT, g_pyT); cudaGetSymbolAddress((void**)&pABT, g_pABT);
    cudaGetSymbolAddress((void**)&pCT, g_pCT);

    cudaFuncSetAttribute(gemm_mma<true, 24>,  cudaFuncAttributeMaxDynamicSharedMemorySize, SMEM_BYTES);
    cudaFuncSetAttribute(gemm_mma<false, 24>, cudaFuncAttributeMaxDynamicSharedMemorySize, SMEM_BYTES);
    cudaFuncSetAttribute(gemm_mma<false, 72>, cudaFuncAttributeMaxDynamicSharedMemorySize, SMEM_BYTES);

    const int mt = (N + 127) / 128;
    dim3 gN(6, mt), gAB(12, mt), gG(6, 1), blk(256);
    dim3 wb(32, 8);

    // ---- launches 0-2: all prep ------------------------------------------
    fsplit<<<(N * DIMV + 255) / 256, 256>>>(x, Bh, Bl, N * DIMV);          // 0
    fsplit<<<(G * DIMV + 255) / 256, 256>>>(y, yh, yl, G * DIMV);          // 1

    WJobs jb;
    jb.j[0]  = { ahW,               ahT[0],         ahT[1],          768,  0    };
    jb.j[1]  = { c0W,               c0T[0],         c0T[1],          768,  0    };
    jb.j[2]  = { c1W,               c1T[0],         c1T[1],          768,  0    };
    jb.j[3]  = { c2W,               c2T[0],         c2T[1],          768,  0    };
    jb.j[4]  = { o2W,               o2T[0],         o2T[1],          768,  0    };
    jb.j[5]  = { pyW,               pyT[0],         pyT[1],          768,  0    };
    jb.j[6]  = { pc1W,              pABT[0],        pABT[1],         768,  0    };
    jb.j[7]  = { pc1W + 768 * 768,  pABT[0] + W768, pABT[1] + W768,  768,  0    };
    jb.j[8]  = { pc1W + 1536 * 768, pCT[0],         pCT[1],          768,  0    };
    jb.j[9]  = { o1W,               o1T[0],         o1T[1],          2304, 0    };
    jb.j[10] = { o1W + 768 * 768,   o1T[0],         o1T[1],          2304, 768  };
    jb.j[11] = { o1W + 1536 * 768,  o1T[0],         o1T[1],          2304, 1536 };
    wsplit_batch<<<dim3(24, 24, 12), wb>>>(jb);                            // 2

    // ---- launches 3-11: ALL gemm_mma -------------------------------------
    gemm_mma<false, 24><<<gN, blk, SMEM_BYTES>>>(Bh, Bl, DIMV, ahT[0], ahT[1], ahb,
                                                 nullptr, Ah, Al, DIMV, N, 1);   // 3
    gemm_mma<false, 24><<<gN, blk, SMEM_BYTES>>>(Ah, Al, DIMV, c0T[0], c0T[1], c0b,
                                                 nullptr, Ch, Cl, 3 * DIMV, N, 1); // 4
    gemm_mma<false, 24><<<gN, blk, SMEM_BYTES>>>(Ch, Cl, 3 * DIMV, c1T[0], c1T[1], c1b,
                                                 nullptr, Ch + DIMV, Cl + DIMV, 3 * DIMV, N, 1); // 5
    gemm_mma<false, 24><<<gN, blk, SMEM_BYTES>>>(Ch + DIMV, Cl + DIMV, 3 * DIMV, c2T[0], c2T[1], c2b,
                                                 nullptr, Ch + 2 * DIMV, Cl + 2 * DIMV, 3 * DIMV, N, 1); // 6
    gemm_mma<false, 72><<<gN, blk, SMEM_BYTES>>>(Ch, Cl, 3 * DIMV, o1T[0], o1T[1], o1b,
                                                 nullptr, Ah, Al, DIMV, N, 1); // 7
    gemm_mma<false, 24><<<gN, blk, SMEM_BYTES>>>(Ah, Al, DIMV, o2T[0], o2T[1], o2b,
                                                 nullptr, Bh, Bl, DIMV, N, 0);   // 8
    gemm_mma<true, 24><<<gAB, blk, SMEM_BYTES>>>(Bh, Bl, DIMV, pABT[0], pABT[1], zero,
                                                 uAB, nullptr, nullptr, 2 * DIMV, N, 0); // 9
    gemm_mma<false, 24><<<gG, blk, SMEM_BYTES>>>(yh, yl, DIMV, pyT[0], pyT[1], pyb,
                                                 nullptr, yph, ypl, DIMV, G, 3); // 10
    gemm_mma<true, 24><<<gG, blk, SMEM_BYTES>>>(yph, ypl, DIMV, pCT[0], pCT[1], pc1b,
                                                t3, nullptr, nullptr, DIMV, G, 0); // 11

    // ---- launch 12: edge head --------------------------------------------
    edge_kernel<<<(E + 7) / 8, 256>>>(uAB, t3, ei, batch, pc2W, pc2b, label, out, E);
}

// round 14
// speedup vs baseline: 1.7517x; 1.5665x over previous
#include <cuda_runtime.h>
#include <cuda_fp16.h>
#include <cstdint>
#include <cstddef>

// ===========================================================================
// LinkPrediction via mma.sync fp16 GEMMs, 2-pass asymmetric emulation:
//   activations: single fp16 (eps 2^-12); weights: fp16 hi+lo (eps 2^-22)
//   X @ W ~= X @ Wh + X @ Wl    (fp32 accumulate)  -- 2 passes, was 3.
// Edge head factorized: concat(emb[s],emb[d],yp)@pc1 = uAB[s,0:768]+uAB[d,768:1536]+t3[g]
// R14: 472G MACs (was 708G). Stage = A(8K)+Wh(8K)+Wl(8K)=24KB, 4-stage
//      cp.async pipeline, BK=32, SW64, 2 CTAs/SM, single-fp16 activations.
// ===========================================================================

#define NM    40000
#define DIMV  768
#define GMAXV 128
#define W768  (768*768)
#define W2304 (768*2304)

// ---------------- device scratch (allocation-free) -------------------------
__device__ __half g_A [NM*DIMV];                     // activations buf A (h0 / z)
__device__ __half g_B [NM*DIMV];                     // activations buf B (x / emb)
__device__ __half g_C [NM*3*DIMV];                   // cat
__device__ float  g_uAB[NM*2*DIMV];                  // fused [uA | uB]
__device__ float  g_t3[GMAXV*DIMV];
__device__ __half g_y [GMAXV*DIMV];
__device__ __half g_yp[GMAXV*DIMV];
__device__ float  g_zero[2*DIMV];
__device__ __half g_ahT[2][W768], g_c0T[2][W768], g_c1T[2][W768], g_c2T[2][W768];
__device__ __half g_o1T[2][W2304];
__device__ __half g_o2T[2][W768], g_pyT[2][W768];
__device__ __half g_pABT[2][2*W768];                 // fused [pc1_A^T ; pc1_B^T]
__device__ __half g_pCT[2][W768];

// ---------------- PTX helpers ----------------------------------------------
__device__ __forceinline__ uint32_t smem_u32(const void* p) {
    uint32_t a;
    asm("{ .reg .u64 t; cvta.to.shared.u64 t, %1; cvt.u32.u64 %0, t; }" : "=r"(a) : "l"(p));
    return a;
}
__device__ __forceinline__ void cpa16(uint32_t dst, const void* src) {
    asm volatile("cp.async.cg.shared.global [%0], [%1], 16;" :: "r"(dst), "l"(src));
}
#define CP_COMMIT() asm volatile("cp.async.commit_group;" ::: "memory")
#define CP_WAIT(n)  asm volatile("cp.async.wait_group %0;" :: "n"(n) : "memory")

__device__ __forceinline__ void ldsm4(uint32_t* r, uint32_t addr) {
    asm volatile("ldmatrix.sync.aligned.m8n8.x4.shared.b16 {%0,%1,%2,%3}, [%4];"
                 : "=r"(r[0]), "=r"(r[1]), "=r"(r[2]), "=r"(r[3]) : "r"(addr));
}
__device__ __forceinline__ void mma_f16(float* c, const uint32_t* a, const uint32_t* b) {
    asm volatile(
        "mma.sync.aligned.m16n8k16.row.col.f32.f16.f16.f32 "
        "{%0,%1,%2,%3}, {%4,%5,%6,%7}, {%8,%9}, {%0,%1,%2,%3};"
        : "+f"(c[0]), "+f"(c[1]), "+f"(c[2]), "+f"(c[3])
        : "r"(a[0]), "r"(a[1]), "r"(a[2]), "r"(a[3]), "r"(b[0]), "r"(b[1]));
}
#define SWZ64(x) ((x) ^ (((x) >> 3) & 0x30))   // SW64 on byte offsets (64B rows)

// ---------------------------------------------------------------------------
// GEMM: D[M, Nn] = act(A[M,K] @ Wt^T + bias), grid = (Nn/128, ceil(M/128))
//   A single fp16 [M,K] (lda); Wt hi/lo fp16 [Nn,K] K-major.  K = 32*NK.
//   FP32OUT=true : fp32 out to Cf.  false: single fp16 to Ch.
//   act: 0 none, 1 relu, 3 leaky(0.4)
// BM=BN=128, BK=32, 256 thr (8 warps, 64x32 warp tiles), SW64 smem,
// 4-stage cp.async (stage = A 8KB | Wh 8KB | Wl 8KB = 24KB), 2 CTAs/SM.
// ---------------------------------------------------------------------------
#define STAGE_BYTES 24576

template<bool FP32OUT, int NK>
__global__ __launch_bounds__(256, 2)
void gemm_mma(const __half* __restrict__ A, int lda,
              const __half* __restrict__ Bhi, const __half* __restrict__ Blo,
              const float* __restrict__ bias,
              float* __restrict__ Cf, __half* __restrict__ Ch,
              int ldc, int M, int act)
{
    constexpr int K = 32 * NK;
    extern __shared__ char smem[];
    const uint32_t base = (smem_u32(smem) + 1023) & ~1023u;
    const int tid  = threadIdx.x;
    const int lane = tid & 31;
    const int w    = tid >> 5;
    const int warpM = w & 1;          // 2 warps along M
    const int warpN = w >> 1;         // 4 warps along N
    const int bm = blockIdx.y * 128;
    const int bn = blockIdx.x * 128;

    // ---- hoisted loader addressing (chunk-invariant) ----------------------
    const int lRow0 = tid >> 2;               // rows 0..63
    const int lRow1 = lRow0 + 64;             // rows 64..127
    const int lCol  = (tid & 3) * 8;          // element col within K32
    const uint32_t sw0 = SWZ64(lRow0 * 64 + lCol * 2);
    const uint32_t sw1 = SWZ64(lRow1 * 64 + lCol * 2);
    int ar0 = bm + lRow0; if (ar0 >= M) ar0 = M - 1;     // clamp (never stored)
    int ar1 = bm + lRow1; if (ar1 >= M) ar1 = M - 1;
    const size_t aOff0 = (size_t)ar0 * lda + lCol;
    const size_t aOff1 = (size_t)ar1 * lda + lCol;
    const size_t bOff0 = (size_t)(bn + lRow0) * K + lCol;
    const size_t bOff1 = (size_t)(bn + lRow1) * K + lCol;

    auto load_stage = [&](int j, int buf) {
        const int k0 = j * 32;
        const uint32_t tb = base + buf * STAGE_BYTES;
        cpa16(tb +         sw0, A   + aOff0 + k0);
        cpa16(tb +  8192 + sw0, Bhi + bOff0 + k0);
        cpa16(tb + 16384 + sw0, Blo + bOff0 + k0);
        cpa16(tb +         sw1, A   + aOff1 + k0);
        cpa16(tb +  8192 + sw1, Bhi + bOff1 + k0);
        cpa16(tb + 16384 + sw1, Blo + bOff1 + k0);
        CP_COMMIT();
    };

    float acc[4][4][4];
    #pragma unroll
    for (int i = 0; i < 4; i++)
        #pragma unroll
        for (int j = 0; j < 4; j++)
            #pragma unroll
            for (int e = 0; e < 4; e++)
                acc[i][j][e] = 0.f;

    // per-lane ldmatrix address components (within-tile, before swizzle)
    const int aRow  = warpM * 64 + (lane & 15);                     // + mf*16
    const int aColE = ((lane >> 4) << 3);                           // + kf*16
    const int bRow  = warpN * 32 + ((lane >> 4) << 3) + (lane & 7); // + nfp*16
    const int bColE = ((lane >> 3) & 1) * 8;                        // + kf*16

    // one kf group: 8 LDSM + 32 HMMA (2 passes) on buffer tb
    auto compute_kf = [&](uint32_t tb, int kf) {
        uint32_t a[4][4];
        #pragma unroll
        for (int mf = 0; mf < 4; mf++) {
            const uint32_t byte = SWZ64((aRow + mf * 16) * 64 + (aColE + kf * 16) * 2);
            ldsm4(a[mf], tb + byte);
        }
        uint32_t bh[4][2], bl[4][2];
        #pragma unroll
        for (int nfp = 0; nfp < 2; nfp++) {
            const uint32_t byte = SWZ64((bRow + nfp * 16) * 64 + (bColE + kf * 16) * 2);
            uint32_t r[4];
            ldsm4(r, tb + 8192 + byte);
            bh[nfp*2][0] = r[0]; bh[nfp*2][1] = r[1];
            bh[nfp*2+1][0] = r[2]; bh[nfp*2+1][1] = r[3];
            ldsm4(r, tb + 16384 + byte);
            bl[nfp*2][0] = r[0]; bl[nfp*2][1] = r[1];
            bl[nfp*2+1][0] = r[2]; bl[nfp*2+1][1] = r[3];
        }
        #pragma unroll
        for (int mf = 0; mf < 4; mf++)
            #pragma unroll
            for (int nf = 0; nf < 4; nf++)
                mma_f16(acc[mf][nf], a[mf], bh[nf]);
        #pragma unroll
        for (int mf = 0; mf < 4; mf++)
            #pragma unroll
            for (int nf = 0; nf < 4; nf++)
                mma_f16(acc[mf][nf], a[mf], bl[nf]);
    };

    load_stage(0, 0);
    load_stage(1, 1);
    load_stage(2, 2);

    #pragma unroll 4
    for (int i = 0; i < NK; i++) {
        // chunk i must be resident; allow up to 2 newer groups pending
        if (i + 2 < NK) { CP_WAIT(2); }
        else if (i + 1 < NK) { CP_WAIT(1); }
        else { CP_WAIT(0); }
        __syncthreads();   // all warps done with compute i-1 before
                           // buffer (i+3)%4 == (i-1)%4 refill below

        const uint32_t tb = base + (i & 3) * STAGE_BYTES;
        compute_kf(tb, 0);
        if (i + 3 < NK) load_stage(i + 3, (i + 3) & 3);
        compute_kf(tb, 1);
    }

    // ---------------- epilogue (registers -> global, no smem) --------------
    #pragma unroll
    for (int mf = 0; mf < 4; mf++) {
        #pragma unroll
        for (int half = 0; half < 2; half++) {
            const int row = bm + warpM * 64 + mf * 16 + (lane >> 2) + half * 8;
            if (row < M) {
                #pragma unroll
                for (int nf = 0; nf < 4; nf++) {
                    const int col = bn + warpN * 32 + nf * 8 + (lane & 3) * 2;
                    const float2 bi = *(const float2*)(bias + col);
                    float v0 = acc[mf][nf][half * 2 + 0] + bi.x;
                    float v1 = acc[mf][nf][half * 2 + 1] + bi.y;
                    if (act == 1) { v0 = fmaxf(v0, 0.f); v1 = fmaxf(v1, 0.f); }
                    else if (act == 3) { v0 = (v0 > 0.f) ? v0 : 0.4f * v0;
                                         v1 = (v1 > 0.f) ? v1 : 0.4f * v1; }
                    if (FP32OUT) {
                        float2 o; o.x = v0; o.y = v1;
                        *(float2*)(Cf + (size_t)row * ldc + col) = o;
                    } else {
                        __half2 hh;
                        hh.x = __float2half_rn(v0);
                        hh.y = __float2half_rn(v1);
                        *(__half2*)(Ch + (size_t)row * ldc + col) = hh;
                    }
                }
            }
        }
    }
}

// ---------------------------------------------------------------------------
// Batched weight transpose + fp16 hi/lo split. Each job transposes a 768x768
// block W[k, n] into hi/lo[n * Kout + k_off + k]. o1 = 3 jobs with Kout=2304.
// ---------------------------------------------------------------------------
struct WJob  { const float* W; __half* hi; __half* lo; int Kout; int k_off; };
struct WJobs { WJob j[12]; };

__global__ void wsplit_batch(WJobs jobs)
{
    __shared__ float t[32][33];
    const WJob jb = jobs.j[blockIdx.z];
    const int Nn = 768;
    const int k0 = blockIdx.x * 32, n0 = blockIdx.y * 32;
    const int tx = threadIdx.x, ty = threadIdx.y;
    #pragma unroll
    for (int i = 0; i < 32; i += 8)
        t[ty + i][tx] = jb.W[(size_t)(k0 + ty + i) * Nn + n0 + tx];
    __syncthreads();
    #pragma unroll
    for (int i = 0; i < 32; i += 8) {
        const float v = t[tx][ty + i];
        const __half h = __float2half_rn(v);
        const size_t o = (size_t)(n0 + ty + i) * jb.Kout + jb.k_off + k0 + tx;
        jb.hi[o] = h;
        jb.lo[o] = __float2half_rn(v - __half2float(h));
    }
}

// fp32 -> single fp16 (activations)
__global__ void fround(const float* __restrict__ s, __half* __restrict__ d, int n)
{
    const int i = blockIdx.x * blockDim.x + threadIdx.x;
    if (i < n) d[i] = __float2half_rn(s[i]);
}

// ---------------------------------------------------------------------------
// Edge head: one warp per edge; uAB holds [uA | uB] rows of 1536.
// ---------------------------------------------------------------------------
__global__ __launch_bounds__(256)
void edge_kernel(const float* __restrict__ uAB,
                 const float* __restrict__ t3,
                 const int* __restrict__ edge_index, const int* __restrict__ batch,
                 const float* __restrict__ w2, const float* __restrict__ b2,
                 const float* __restrict__ label, float* __restrict__ out, int E)
{
    const int e = blockIdx.x * 8 + (threadIdx.x >> 5);
    if (e >= E) return;
    const int lane = threadIdx.x & 31;
    const int s = edge_index[e];
    const int d = edge_index[E + e];
    const int g = batch[s];

    const float4* a = (const float4*)(uAB + (size_t)s * (2 * DIMV));
    const float4* b = (const float4*)(uAB + (size_t)d * (2 * DIMV) + DIMV);
    const float4* t = (const float4*)(t3 + (size_t)g * DIMV);
    const float4* wv = (const float4*)w2;

    float p0 = 0.f, p1 = 0.f;
    #pragma unroll
    for (int it = 0; it < 6; it++) {
        const int q = it * 32 + lane;
        float4 av = a[q], bv = b[q], tv = t[q];
        float4 w0 = wv[2 * q], w1 = wv[2 * q + 1];
        float v0 = fmaxf(av.x + bv.x + tv.x, 0.f);
        float v1 = fmaxf(av.y + bv.y + tv.y, 0.f);
        float v2 = fmaxf(av.z + bv.z + tv.z, 0.f);
        float v3 = fmaxf(av.w + bv.w + tv.w, 0.f);
        p0 = fmaf(v0, w0.x, p0); p0 = fmaf(v1, w0.z, p0);
        p0 = fmaf(v2, w1.x, p0); p0 = fmaf(v3, w1.z, p0);
        p1 = fmaf(v0, w0.y, p1); p1 = fmaf(v1, w0.w, p1);
        p1 = fmaf(v2, w1.y, p1); p1 = fmaf(v3, w1.w, p1);
    }
    #pragma unroll
    for (int o = 16; o > 0; o >>= 1) {
        p0 += __shfl_xor_sync(0xFFFFFFFFu, p0, o);
        p1 += __shfl_xor_sync(0xFFFFFFFFu, p1, o);
    }
    if (lane == 0) {
        out[2 * e]     = 1.f / (1.f + expf(-(p0 + b2[0])));
        out[2 * e + 1] = 1.f / (1.f + expf(-(p1 + b2[1])));
        out[2 * E + e] = label[e];
    }
}

// ---------------------------------------------------------------------------
// Host launcher.  Stream order: 0-2 prep, 3-11 gemm_mma, 12 edge.
// ---------------------------------------------------------------------------
static const int SMEM_BYTES = 1024 + 4 * STAGE_BYTES;   // 99328 per CTA

extern "C" void kernel_launch(void* const* d_in, const int* in_sizes, int n_in,
                              void* d_out, int out_size)
{
    const float* x     = (const float*)d_in[0];
    const int*   ei    = (const int*)  d_in[1];
    const int*   batch = (const int*)  d_in[2];
    const float* y     = (const float*)d_in[5];
    const float* label = (const float*)d_in[6];
    const float* ahW = (const float*)d_in[7],  *ahb = (const float*)d_in[8];
    const float* c0W = (const float*)d_in[9],  *c0b = (const float*)d_in[10];
    const float* c1W = (const float*)d_in[11], *c1b = (const float*)d_in[12];
    const float* c2W = (const float*)d_in[13], *c2b = (const float*)d_in[14];
    const float* o1W = (const float*)d_in[15], *o1b = (const float*)d_in[16];
    const float* o2W = (const float*)d_in[17], *o2b = (const float*)d_in[18];
    const float* pyW = (const float*)d_in[19], *pyb = (const float*)d_in[20];
    const float* pc1W = (const float*)d_in[21], *pc1b = (const float*)d_in[22];
    const float* pc2W = (const float*)d_in[23], *pc2b = (const float*)d_in[24];
    float* out = (float*)d_out;

    const int N = in_sizes[2];
    const int E = in_sizes[6];
    const int G = in_sizes[5] / DIMV;
    (void)n_in; (void)out_size;

    __half *A, *B, *C, *yh, *yp;
    float *uAB, *t3, *zero;
    __half (*ahT)[W768], (*c0T)[W768], (*c1T)[W768], (*c2T)[W768],
           (*o2T)[W768], (*pyT)[W768], (*pCT)[W768];
    __half (*o1T)[W2304];
    __half (*pABT)[2*W768];
    cudaGetSymbolAddress((void**)&A, g_A);     cudaGetSymbolAddress((void**)&B, g_B);
    cudaGetSymbolAddress((void**)&C, g_C);
    cudaGetSymbolAddress((void**)&yh, g_y);    cudaGetSymbolAddress((void**)&yp, g_yp);
    cudaGetSymbolAddress((void**)&uAB, g_uAB);
    cudaGetSymbolAddress((void**)&t3, g_t3);   cudaGetSymbolAddress((void**)&zero, g_zero);
    cudaGetSymbolAddress((void**)&ahT, g_ahT); cudaGetSymbolAddress((void**)&c0T, g_c0T);
    cudaGetSymbolAddress((void**)&c1T, g_c1T); cudaGetSymbolAddress((void**)&c2T, g_c2T);
    cudaGetSymbolAddress((void**)&o1T, g_o1T); cudaGetSymbolAddress((void**)&o2T, g_o2T);
    cudaGetSymbolAddress((void**)&pyT, g_pyT); cudaGetSymbolAddress((void**)&pABT, g_pABT);
    cudaGetSymbolAddress((void**)&pCT, g_pCT);

    cudaFuncSetAttribute(gemm_mma<true, 24>,  cudaFuncAttributeMaxDynamicSharedMemorySize, SMEM_BYTES);
    cudaFuncSetAttribute(gemm_mma<false, 24>, cudaFuncAttributeMaxDynamicSharedMemorySize, SMEM_BYTES);
    cudaFuncSetAttribute(gemm_mma<false, 72>, cudaFuncAttributeMaxDynamicSharedMemorySize, SMEM_BYTES);

    const int mt = (N + 127) / 128;
    dim3 gN(6, mt), gAB(12, mt), gG(6, 1), blk(256);
    dim3 wb(32, 8);

    // ---- launches 0-2: all prep ------------------------------------------
    fround<<<(N * DIMV + 255) / 256, 256>>>(x, B, N * DIMV);               // 0
    fround<<<(G * DIMV + 255) / 256, 256>>>(y, yh, G * DIMV);              // 1

    WJobs jb;
    jb.j[0]  = { ahW,               ahT[0],         ahT[1],          768,  0    };
    jb.j[1]  = { c0W,               c0T[0],         c0T[1],          768,  0    };
    jb.j[2]  = { c1W,               c1T[0],         c1T[1],          768,  0    };
    jb.j[3]  = { c2W,               c2T[0],         c2T[1],          768,  0    };
    jb.j[4]  = { o2W,               o2T[0],         o2T[1],          768,  0    };
    jb.j[5]  = { pyW,               pyT[0],         pyT[1],          768,  0    };
    jb.j[6]  = { pc1W,              pABT[0],        pABT[1],         768,  0    };
    jb.j[7]  = { pc1W + 768 * 768,  pABT[0] + W768, pABT[1] + W768,  768,  0    };
    jb.j[8]  = { pc1W + 1536 * 768, pCT[0],         pCT[1],          768,  0    };
    jb.j[9]  = { o1W,               o1T[0],         o1T[1],          2304, 0    };
    jb.j[10] = { o1W + 768 * 768,   o1T[0],         o1T[1],          2304, 768  };
    jb.j[11] = { o1W + 1536 * 768,  o1T[0],         o1T[1],          2304, 1536 };
    wsplit_batch<<<dim3(24, 24, 12), wb>>>(jb);                            // 2

    // ---- launches 3-11: ALL gemm_mma -------------------------------------
    gemm_mma<false, 24><<<gN, blk, SMEM_BYTES>>>(B, DIMV, ahT[0], ahT[1], ahb,
                                                 nullptr, A, DIMV, N, 1);         // 3
    gemm_mma<false, 24><<<gN, blk, SMEM_BYTES>>>(A, DIMV, c0T[0], c0T[1], c0b,
                                                 nullptr, C, 3 * DIMV, N, 1);     // 4
    gemm_mma<false, 24><<<gN, blk, SMEM_BYTES>>>(C, 3 * DIMV, c1T[0], c1T[1], c1b,
                                                 nullptr, C + DIMV, 3 * DIMV, N, 1); // 5
    gemm_mma<false, 24><<<gN, blk, SMEM_BYTES>>>(C + DIMV, 3 * DIMV, c2T[0], c2T[1], c2b,
                                                 nullptr, C + 2 * DIMV, 3 * DIMV, N, 1); // 6
    gemm_mma<false, 72><<<gN, blk, SMEM_BYTES>>>(C, 3 * DIMV, o1T[0], o1T[1], o1b,
                                                 nullptr, A, DIMV, N, 1);         // 7
    gemm_mma<false, 24><<<gN, blk, SMEM_BYTES>>>(A, DIMV, o2T[0], o2T[1], o2b,
                                                 nullptr, B, DIMV, N, 0);         // 8
    gemm_mma<true, 24><<<gAB, blk, SMEM_BYTES>>>(B, DIMV, pABT[0], pABT[1], zero,
                                                 uAB, nullptr, 2 * DIMV, N, 0);   // 9
    gemm_mma<false, 24><<<gG, blk, SMEM_BYTES>>>(yh, DIMV, pyT[0], pyT[1], pyb,
                                                 nullptr, yp, DIMV, G, 3);        // 10
    gemm_mma<true, 24><<<gG, blk, SMEM_BYTES>>>(yp, DIMV, pCT[0], pCT[1], pc1b,
                                                t3, nullptr, DIMV, G, 0);         // 11

    // ---- launch 12: edge head --------------------------------------------
    edge_kernel<<<(E + 7) / 8, 256>>>(uAB, t3, ei, batch, pc2W, pc2b, label, out, E);
}

// round 15
// speedup vs baseline: 2.9555x; 1.6872x over previous
#include <cuda_runtime.h>
#include <cuda_fp16.h>
#include <cstdint>
#include <cstddef>

// ===========================================================================
// LinkPrediction via mma.sync fp16 GEMMs, SINGLE-pass fp16:
//   activations AND weights single fp16 (eps 2^-12 each); fp32 accumulate.
//   Validated error model (R5/R14 calibration): final rel_err ~ 0.5-0.7x
//   per-operand eps -> predicted ~1.9e-4 << 1e-3 threshold.
// Edge head factorized: concat(emb[s],emb[d],yp)@pc1 = uAB[s,0:768]+uAB[d,768:1536]+t3[g]
// R15: 236G MACs (was 472G). Stage = A(8K)+W(8K)=16KB, 4-stage cp.async,
//      BK=32, SW64, 2 CTAs/SM.
// ===========================================================================

#define NM    40000
#define DIMV  768
#define GMAXV 128
#define W768  (768*768)
#define W2304 (768*2304)

// ---------------- device scratch (allocation-free) -------------------------
__device__ __half g_A [NM*DIMV];                     // activations buf A (h0 / z)
__device__ __half g_B [NM*DIMV];                     // activations buf B (x / emb)
__device__ __half g_C [NM*3*DIMV];                   // cat
__device__ float  g_uAB[NM*2*DIMV];                  // fused [uA | uB]
__device__ float  g_t3[GMAXV*DIMV];
__device__ __half g_y [GMAXV*DIMV];
__device__ __half g_yp[GMAXV*DIMV];
__device__ float  g_zero[2*DIMV];
__device__ __half g_ahT[W768], g_c0T[W768], g_c1T[W768], g_c2T[W768];
__device__ __half g_o1T[W2304];
__device__ __half g_o2T[W768], g_pyT[W768];
__device__ __half g_pABT[2*W768];                    // fused [pc1_A^T ; pc1_B^T]
__device__ __half g_pCT[W768];

// ---------------- PTX helpers ----------------------------------------------
__device__ __forceinline__ uint32_t smem_u32(const void* p) {
    uint32_t a;
    asm("{ .reg .u64 t; cvta.to.shared.u64 t, %1; cvt.u32.u64 %0, t; }" : "=r"(a) : "l"(p));
    return a;
}
__device__ __forceinline__ void cpa16(uint32_t dst, const void* src) {
    asm volatile("cp.async.cg.shared.global [%0], [%1], 16;" :: "r"(dst), "l"(src));
}
#define CP_COMMIT() asm volatile("cp.async.commit_group;" ::: "memory")
#define CP_WAIT(n)  asm volatile("cp.async.wait_group %0;" :: "n"(n) : "memory")

__device__ __forceinline__ void ldsm4(uint32_t* r, uint32_t addr) {
    asm volatile("ldmatrix.sync.aligned.m8n8.x4.shared.b16 {%0,%1,%2,%3}, [%4];"
                 : "=r"(r[0]), "=r"(r[1]), "=r"(r[2]), "=r"(r[3]) : "r"(addr));
}
__device__ __forceinline__ void mma_f16(float* c, const uint32_t* a, const uint32_t* b) {
    asm volatile(
        "mma.sync.aligned.m16n8k16.row.col.f32.f16.f16.f32 "
        "{%0,%1,%2,%3}, {%4,%5,%6,%7}, {%8,%9}, {%0,%1,%2,%3};"
        : "+f"(c[0]), "+f"(c[1]), "+f"(c[2]), "+f"(c[3])
        : "r"(a[0]), "r"(a[1]), "r"(a[2]), "r"(a[3]), "r"(b[0]), "r"(b[1]));
}
#define SWZ64(x) ((x) ^ (((x) >> 3) & 0x30))   // SW64 on byte offsets (64B rows)

// ---------------------------------------------------------------------------
// GEMM: D[M, Nn] = act(A[M,K] @ Wt^T + bias), grid = (Nn/128, ceil(M/128))
//   A fp16 [M,K] (lda); Wt fp16 [Nn,K] K-major.  K = 32*NK.
//   FP32OUT=true : fp32 out to Cf.  false: fp16 to Ch.
//   act: 0 none, 1 relu, 3 leaky(0.4)
// BM=BN=128, BK=32, 256 thr (8 warps, 64x32 warp tiles), SW64 smem,
// 4-stage cp.async (stage = A 8KB | W 8KB = 16KB), 2 CTAs/SM.
// ---------------------------------------------------------------------------
#define STAGE_BYTES 16384

template<bool FP32OUT, int NK>
__global__ __launch_bounds__(256, 2)
void gemm_mma(const __half* __restrict__ A, int lda,
              const __half* __restrict__ Wt,
              const float* __restrict__ bias,
              float* __restrict__ Cf, __half* __restrict__ Ch,
              int ldc, int M, int act)
{
    constexpr int K = 32 * NK;
    extern __shared__ char smem[];
    const uint32_t base = (smem_u32(smem) + 1023) & ~1023u;
    const int tid  = threadIdx.x;
    const int lane = tid & 31;
    const int w    = tid >> 5;
    const int warpM = w & 1;          // 2 warps along M
    const int warpN = w >> 1;         // 4 warps along N
    const int bm = blockIdx.y * 128;
    const int bn = blockIdx.x * 128;

    // ---- hoisted loader addressing (chunk-invariant) ----------------------
    const int lRow0 = tid >> 2;               // rows 0..63
    const int lRow1 = lRow0 + 64;             // rows 64..127
    const int lCol  = (tid & 3) * 8;          // element col within K32
    const uint32_t sw0 = SWZ64(lRow0 * 64 + lCol * 2);
    const uint32_t sw1 = SWZ64(lRow1 * 64 + lCol * 2);
    int ar0 = bm + lRow0; if (ar0 >= M) ar0 = M - 1;     // clamp (never stored)
    int ar1 = bm + lRow1; if (ar1 >= M) ar1 = M - 1;
    const size_t aOff0 = (size_t)ar0 * lda + lCol;
    const size_t aOff1 = (size_t)ar1 * lda + lCol;
    const size_t bOff0 = (size_t)(bn + lRow0) * K + lCol;
    const size_t bOff1 = (size_t)(bn + lRow1) * K + lCol;

    auto load_stage = [&](int j, int buf) {
        const int k0 = j * 32;
        const uint32_t tb = base + buf * STAGE_BYTES;
        cpa16(tb +        sw0, A  + aOff0 + k0);
        cpa16(tb + 8192 + sw0, Wt + bOff0 + k0);
        cpa16(tb +        sw1, A  + aOff1 + k0);
        cpa16(tb + 8192 + sw1, Wt + bOff1 + k0);
        CP_COMMIT();
    };

    float acc[4][4][4];
    #pragma unroll
    for (int i = 0; i < 4; i++)
        #pragma unroll
        for (int j = 0; j < 4; j++)
            #pragma unroll
            for (int e = 0; e < 4; e++)
                acc[i][j][e] = 0.f;

    // per-lane ldmatrix address components (within-tile, before swizzle)
    const int aRow  = warpM * 64 + (lane & 15);                     // + mf*16
    const int aColE = ((lane >> 4) << 3);                           // + kf*16
    const int bRow  = warpN * 32 + ((lane >> 4) << 3) + (lane & 7); // + nfp*16
    const int bColE = ((lane >> 3) & 1) * 8;                        // + kf*16

    // one kf group: 6 LDSM + 16 HMMA on buffer tb
    auto compute_kf = [&](uint32_t tb, int kf) {
        uint32_t a[4][4];
        #pragma unroll
        for (int mf = 0; mf < 4; mf++) {
            const uint32_t byte = SWZ64((aRow + mf * 16) * 64 + (aColE + kf * 16) * 2);
            ldsm4(a[mf], tb + byte);
        }
        uint32_t bb[4][2];
        #pragma unroll
        for (int nfp = 0; nfp < 2; nfp++) {
            const uint32_t byte = SWZ64((bRow + nfp * 16) * 64 + (bColE + kf * 16) * 2);
            uint32_t r[4];
            ldsm4(r, tb + 8192 + byte);
            bb[nfp*2][0] = r[0]; bb[nfp*2][1] = r[1];
            bb[nfp*2+1][0] = r[2]; bb[nfp*2+1][1] = r[3];
        }
        #pragma unroll
        for (int mf = 0; mf < 4; mf++)
            #pragma unroll
            for (int nf = 0; nf < 4; nf++)
                mma_f16(acc[mf][nf], a[mf], bb[nf]);
    };

    load_stage(0, 0);
    load_stage(1, 1);
    load_stage(2, 2);

    #pragma unroll 4
    for (int i = 0; i < NK; i++) {
        // chunk i must be resident; allow up to 2 newer groups pending
        if (i + 2 < NK) { CP_WAIT(2); }
        else if (i + 1 < NK) { CP_WAIT(1); }
        else { CP_WAIT(0); }
        __syncthreads();   // all warps done with compute i-1 before
                           // buffer (i+3)%4 == (i-1)%4 refill below

        const uint32_t tb = base + (i & 3) * STAGE_BYTES;
        compute_kf(tb, 0);
        if (i + 3 < NK) load_stage(i + 3, (i + 3) & 3);
        compute_kf(tb, 1);
    }

    // ---------------- epilogue (registers -> global, no smem) --------------
    #pragma unroll
    for (int mf = 0; mf < 4; mf++) {
        #pragma unroll
        for (int half = 0; half < 2; half++) {
            const int row = bm + warpM * 64 + mf * 16 + (lane >> 2) + half * 8;
            if (row < M) {
                #pragma unroll
                for (int nf = 0; nf < 4; nf++) {
                    const int col = bn + warpN * 32 + nf * 8 + (lane & 3) * 2;
                    const float2 bi = *(const float2*)(bias + col);
                    float v0 = acc[mf][nf][half * 2 + 0] + bi.x;
                    float v1 = acc[mf][nf][half * 2 + 1] + bi.y;
                    if (act == 1) { v0 = fmaxf(v0, 0.f); v1 = fmaxf(v1, 0.f); }
                    else if (act == 3) { v0 = (v0 > 0.f) ? v0 : 0.4f * v0;
                                         v1 = (v1 > 0.f) ? v1 : 0.4f * v1; }
                    if (FP32OUT) {
                        float2 o; o.x = v0; o.y = v1;
                        *(float2*)(Cf + (size_t)row * ldc + col) = o;
                    } else {
                        __half2 hh;
                        hh.x = __float2half_rn(v0);
                        hh.y = __float2half_rn(v1);
                        *(__half2*)(Ch + (size_t)row * ldc + col) = hh;
                    }
                }
            }
        }
    }
}

// ---------------------------------------------------------------------------
// Batched weight transpose to fp16. Each job transposes a 768x768 block
// W[k, n] into T[n * Kout + k_off + k]. o1 = 3 jobs with Kout=2304.
// ---------------------------------------------------------------------------
struct WJob  { const float* W; __half* T; int Kout; int k_off; };
struct WJobs { WJob j[12]; };

__global__ void wsplit_batch(WJobs jobs)
{
    __shared__ float t[32][33];
    const WJob jb = jobs.j[blockIdx.z];
    const int Nn = 768;
    const int k0 = blockIdx.x * 32, n0 = blockIdx.y * 32;
    const int tx = threadIdx.x, ty = threadIdx.y;
    #pragma unroll
    for (int i = 0; i < 32; i += 8)
        t[ty + i][tx] = jb.W[(size_t)(k0 + ty + i) * Nn + n0 + tx];
    __syncthreads();
    #pragma unroll
    for (int i = 0; i < 32; i += 8) {
        const size_t o = (size_t)(n0 + ty + i) * jb.Kout + jb.k_off + k0 + tx;
        jb.T[o] = __float2half_rn(t[tx][ty + i]);
    }
}

// fp32 -> fp16 (activations)
__global__ void fround(const float* __restrict__ s, __half* __restrict__ d, int n)
{
    const int i = blockIdx.x * blockDim.x + threadIdx.x;
    if (i < n) d[i] = __float2half_rn(s[i]);
}

// ---------------------------------------------------------------------------
// Edge head: one warp per edge; uAB holds [uA | uB] rows of 1536.
// ---------------------------------------------------------------------------
__global__ __launch_bounds__(256)
void edge_kernel(const float* __restrict__ uAB,
                 const float* __restrict__ t3,
                 const int* __restrict__ edge_index, const int* __restrict__ batch,
                 const float* __restrict__ w2, const float* __restrict__ b2,
                 const float* __restrict__ label, float* __restrict__ out, int E)
{
    const int e = blockIdx.x * 8 + (threadIdx.x >> 5);
    if (e >= E) return;
    const int lane = threadIdx.x & 31;
    const int s = edge_index[e];
    const int d = edge_index[E + e];
    const int g = batch[s];

    const float4* a = (const float4*)(uAB + (size_t)s * (2 * DIMV));
    const float4* b = (const float4*)(uAB + (size_t)d * (2 * DIMV) + DIMV);
    const float4* t = (const float4*)(t3 + (size_t)g * DIMV);
    const float4* wv = (const float4*)w2;

    float p0 = 0.f, p1 = 0.f;
    #pragma unroll
    for (int it = 0; it < 6; it++) {
        const int q = it * 32 + lane;
        float4 av = a[q], bv = b[q], tv = t[q];
        float4 w0 = wv[2 * q], w1 = wv[2 * q + 1];
        float v0 = fmaxf(av.x + bv.x + tv.x, 0.f);
        float v1 = fmaxf(av.y + bv.y + tv.y, 0.f);
        float v2 = fmaxf(av.z + bv.z + tv.z, 0.f);
        float v3 = fmaxf(av.w + bv.w + tv.w, 0.f);
        p0 = fmaf(v0, w0.x, p0); p0 = fmaf(v1, w0.z, p0);
        p0 = fmaf(v2, w1.x, p0); p0 = fmaf(v3, w1.z, p0);
        p1 = fmaf(v0, w0.y, p1); p1 = fmaf(v1, w0.w, p1);
        p1 = fmaf(v2, w1.y, p1); p1 = fmaf(v3, w1.w, p1);
    }
    #pragma unroll
    for (int o = 16; o > 0; o >>= 1) {
        p0 += __shfl_xor_sync(0xFFFFFFFFu, p0, o);
        p1 += __shfl_xor_sync(0xFFFFFFFFu, p1, o);
    }
    if (lane == 0) {
        out[2 * e]     = 1.f / (1.f + expf(-(p0 + b2[0])));
        out[2 * e + 1] = 1.f / (1.f + expf(-(p1 + b2[1])));
        out[2 * E + e] = label[e];
    }
}

// ---------------------------------------------------------------------------
// Host launcher.  Stream order: 0-2 prep, 3-11 gemm_mma, 12 edge.
// ---------------------------------------------------------------------------
static const int SMEM_BYTES = 1024 + 4 * STAGE_BYTES;   // 66560 per CTA

extern "C" void kernel_launch(void* const* d_in, const int* in_sizes, int n_in,
                              void* d_out, int out_size)
{
    const float* x     = (const float*)d_in[0];
    const int*   ei    = (const int*)  d_in[1];
    const int*   batch = (const int*)  d_in[2];
    const float* y     = (const float*)d_in[5];
    const float* label = (const float*)d_in[6];
    const float* ahW = (const float*)d_in[7],  *ahb = (const float*)d_in[8];
    const float* c0W = (const float*)d_in[9],  *c0b = (const float*)d_in[10];
    const float* c1W = (const float*)d_in[11], *c1b = (const float*)d_in[12];
    const float* c2W = (const float*)d_in[13], *c2b = (const float*)d_in[14];
    const float* o1W = (const float*)d_in[15], *o1b = (const float*)d_in[16];
    const float* o2W = (const float*)d_in[17], *o2b = (const float*)d_in[18];
    const float* pyW = (const float*)d_in[19], *pyb = (const float*)d_in[20];
    const float* pc1W = (const float*)d_in[21], *pc1b = (const float*)d_in[22];
    const float* pc2W = (const float*)d_in[23], *pc2b = (const float*)d_in[24];
    float* out = (float*)d_out;

    const int N = in_sizes[2];
    const int E = in_sizes[6];
    const int G = in_sizes[5] / DIMV;
    (void)n_in; (void)out_size;

    __half *A, *B, *C, *yh, *yp;
    float *uAB, *t3, *zero;
    __half *ahT, *c0T, *c1T, *c2T, *o2T, *pyT, *pCT, *o1T, *pABT;
    cudaGetSymbolAddress((void**)&A, g_A);     cudaGetSymbolAddress((void**)&B, g_B);
    cudaGetSymbolAddress((void**)&C, g_C);
    cudaGetSymbolAddress((void**)&yh, g_y);    cudaGetSymbolAddress((void**)&yp, g_yp);
    cudaGetSymbolAddress((void**)&uAB, g_uAB);
    cudaGetSymbolAddress((void**)&t3, g_t3);   cudaGetSymbolAddress((void**)&zero, g_zero);
    cudaGetSymbolAddress((void**)&ahT, g_ahT); cudaGetSymbolAddress((void**)&c0T, g_c0T);
    cudaGetSymbolAddress((void**)&c1T, g_c1T); cudaGetSymbolAddress((void**)&c2T, g_c2T);
    cudaGetSymbolAddress((void**)&o1T, g_o1T); cudaGetSymbolAddress((void**)&o2T, g_o2T);
    cudaGetSymbolAddress((void**)&pyT, g_pyT); cudaGetSymbolAddress((void**)&pABT, g_pABT);
    cudaGetSymbolAddress((void**)&pCT, g_pCT);

    cudaFuncSetAttribute(gemm_mma<true, 24>,  cudaFuncAttributeMaxDynamicSharedMemorySize, SMEM_BYTES);
    cudaFuncSetAttribute(gemm_mma<false, 24>, cudaFuncAttributeMaxDynamicSharedMemorySize, SMEM_BYTES);
    cudaFuncSetAttribute(gemm_mma<false, 72>, cudaFuncAttributeMaxDynamicSharedMemorySize, SMEM_BYTES);

    const int mt = (N + 127) / 128;
    dim3 gN(6, mt), gAB(12, mt), gG(6, 1), blk(256);
    dim3 wb(32, 8);

    // ---- launches 0-2: all prep ------------------------------------------
    fround<<<(N * DIMV + 255) / 256, 256>>>(x, B, N * DIMV);               // 0
    fround<<<(G * DIMV + 255) / 256, 256>>>(y, yh, G * DIMV);              // 1

    WJobs jb;
    jb.j[0]  = { ahW,               ahT,          768,  0    };
    jb.j[1]  = { c0W,               c0T,          768,  0    };
    jb.j[2]  = { c1W,               c1T,          768,  0    };
    jb.j[3]  = { c2W,               c2T,          768,  0    };
    jb.j[4]  = { o2W,               o2T,          768,  0    };
    jb.j[5]  = { pyW,               pyT,          768,  0    };
    jb.j[6]  = { pc1W,              pABT,         768,  0    };
    jb.j[7]  = { pc1W + 768 * 768,  pABT + W768,  768,  0    };
    jb.j[8]  = { pc1W + 1536 * 768, pCT,          768,  0    };
    jb.j[9]  = { o1W,               o1T,          2304, 0    };
    jb.j[10] = { o1W + 768 * 768,   o1T,          2304, 768  };
    jb.j[11] = { o1W + 1536 * 768,  o1T,          2304, 1536 };
    wsplit_batch<<<dim3(24, 24, 12), wb>>>(jb);                            // 2

    // ---- launches 3-11: ALL gemm_mma -------------------------------------
    gemm_mma<false, 24><<<gN, blk, SMEM_BYTES>>>(B, DIMV, ahT, ahb,
                                                 nullptr, A, DIMV, N, 1);         // 3
    gemm_mma<false, 24><<<gN, blk, SMEM_BYTES>>>(A, DIMV, c0T, c0b,
                                                 nullptr, C, 3 * DIMV, N, 1);     // 4
    gemm_mma<false, 24><<<gN, blk, SMEM_BYTES>>>(C, 3 * DIMV, c1T, c1b,
                                                 nullptr, C + DIMV, 3 * DIMV, N, 1); // 5
    gemm_mma<false, 24><<<gN, blk, SMEM_BYTES>>>(C + DIMV, 3 * DIMV, c2T, c2b,
                                                 nullptr, C + 2 * DIMV, 3 * DIMV, N, 1); // 6
    gemm_mma<false, 72><<<gN, blk, SMEM_BYTES>>>(C, 3 * DIMV, o1T, o1b,
                                                 nullptr, A, DIMV, N, 1);         // 7
    gemm_mma<false, 24><<<gN, blk, SMEM_BYTES>>>(A, DIMV, o2T, o2b,
                                                 nullptr, B, DIMV, N, 0);         // 8
    gemm_mma<true, 24><<<gAB, blk, SMEM_BYTES>>>(B, DIMV, pABT, zero,
                                                 uAB, nullptr, 2 * DIMV, N, 0);   // 9
    gemm_mma<false, 24><<<gG, blk, SMEM_BYTES>>>(yh, DIMV, pyT, pyb,
                                                 nullptr, yp, DIMV, G, 3);        // 10
    gemm_mma<true, 24><<<gG, blk, SMEM_BYTES>>>(yp, DIMV, pCT, pc1b,
                                                t3, nullptr, DIMV, G, 0);         // 11

    // ---- launch 12: edge head --------------------------------------------
    edge_kernel<<<(E + 7) / 8, 256>>>(uAB, t3, ei, batch, pc2W, pc2b, label, out, E);
}